// round 13
// baseline (speedup 1.0000x reference)
#include <cuda_runtime.h>
#include <cuda_fp16.h>
#include <cuda_fp8.h>
#include <math.h>

#define NT 100000
#define NB 50
#define NE 1600000
#define NV 15000
#define D  128
#define NPG (NT / NB)          // 2000 nodes per graph
#define CAP 64                 // bucket capacity per node (P[deg>64] ~ 1e-13)

#define ZBLK ((NT + 255) / 256)   // 391 zero blocks
#define GBLK 256                  // gemm blocks
#define PRE_GRID (ZBLK + GBLK + 1)

// ---------------- static device scratch (no allocations allowed) ----------------
__device__ __align__(16) unsigned char g_We1q[(size_t)NV * D]; // fp8 e4m3 word_embeds@W1 (1.9MB)
__device__ int   g_count[NT];                                  // write cursor -> deg
__device__ __align__(16) uint2 g_bedge[(size_t)NT * CAP];      // bucketed edges, 51.2MB
                                                               // .x = (wid<<17)|src, .y = f32 bits(w)
__device__ float g_z[NT];                                      // z[n] = lrelu(h1[n]) . u
__device__ __align__(16) float g_u[D];                         // u = W2 @ W_out
__device__ float g_cscal;                                      // c = b2 . W_out
__device__ float g_gsum[NB];                                   // per-graph sum of h2.W_out

// ---------------- fused: zero counters | We1 GEMM (fp8 out) | u,c precompute ----------------
__global__ void k_pre(const float* __restrict__ emb, const float* __restrict__ W1,
                      const float* __restrict__ W2, const float* __restrict__ Wout,
                      const float* __restrict__ b2) {
    int bx = blockIdx.x;
    int tid = threadIdx.x;

    if (bx < ZBLK) {
        // ---- zero cursors + graph sums ----
        int i = bx * 256 + tid;
        if (i < NT) g_count[i] = 0;
        if (bx == 0 && tid < NB) g_gsum[tid] = 0.f;
        return;
    }
    if (bx < ZBLK + GBLK) {
        // ---- We1 = emb @ W1, fp8 e4m3 output, 4-row register blocking ----
        int lane = tid & 31;
        int warp = (bx - ZBLK) * 8 + (tid >> 5);   // 2048 warps
        const int nw = GBLK * 8;
        for (int rb = warp * 4; rb < NV; rb += nw * 4) {
            float4 h[4], acc[4];
#pragma unroll
            for (int r = 0; r < 4; ++r) {
                h[r] = *reinterpret_cast<const float4*>(emb + (size_t)(rb + r) * D + 4 * lane);
                acc[r] = make_float4(0.f, 0.f, 0.f, 0.f);
            }
#pragma unroll 2
            for (int q = 0; q < 32; ++q) {
                float4 w0 = __ldg(reinterpret_cast<const float4*>(W1 + (4 * q + 0) * D + 4 * lane));
                float4 w1 = __ldg(reinterpret_cast<const float4*>(W1 + (4 * q + 1) * D + 4 * lane));
                float4 w2 = __ldg(reinterpret_cast<const float4*>(W1 + (4 * q + 2) * D + 4 * lane));
                float4 w3 = __ldg(reinterpret_cast<const float4*>(W1 + (4 * q + 3) * D + 4 * lane));
#pragma unroll
                for (int r = 0; r < 4; ++r) {
                    float hx = __shfl_sync(0xffffffffu, h[r].x, q);
                    float hy = __shfl_sync(0xffffffffu, h[r].y, q);
                    float hz = __shfl_sync(0xffffffffu, h[r].z, q);
                    float hw = __shfl_sync(0xffffffffu, h[r].w, q);
                    acc[r].x += hx * w0.x + hy * w1.x + hz * w2.x + hw * w3.x;
                    acc[r].y += hx * w0.y + hy * w1.y + hz * w2.y + hw * w3.y;
                    acc[r].z += hx * w0.z + hy * w1.z + hz * w2.z + hw * w3.z;
                    acc[r].w += hx * w0.w + hy * w1.w + hz * w2.w + hw * w3.w;
                }
            }
#pragma unroll
            for (int r = 0; r < 4; ++r) {
                unsigned b0 = __nv_cvt_float_to_fp8(acc[r].x, __NV_SATFINITE, __NV_E4M3);
                unsigned b1 = __nv_cvt_float_to_fp8(acc[r].y, __NV_SATFINITE, __NV_E4M3);
                unsigned b2q = __nv_cvt_float_to_fp8(acc[r].z, __NV_SATFINITE, __NV_E4M3);
                unsigned b3 = __nv_cvt_float_to_fp8(acc[r].w, __NV_SATFINITE, __NV_E4M3);
                unsigned pk = b0 | (b1 << 8) | (b2q << 16) | (b3 << 24);
                reinterpret_cast<unsigned*>(g_We1q + (size_t)(rb + r) * D)[lane] = pk;
            }
        }
        return;
    }
    // ---- last block: u = W2 @ W_out, c = b2 . W_out ----
    if (tid < D) {
        float s = 0.f;
        for (int j = 0; j < D; ++j) s += W2[tid * D + j] * Wout[j];
        g_u[tid] = s;
    }
    if (tid == 0) {
        float c = 0.f;
        for (int j = 0; j < D; ++j) c += b2[j] * Wout[j];
        g_cscal = c;
    }
}

// ---------------- bucket scatter (single pass; cursor atomics double as deg) ----------------
__global__ void k_scatter(const int* __restrict__ src, const int* __restrict__ dst,
                          const float* __restrict__ ew,
                          const int* __restrict__ node_ids) {
    int stride = gridDim.x * blockDim.x;
    for (int e = blockIdx.x * blockDim.x + threadIdx.x; e < NE; e += stride) {
        int s = src[e];
        int d = dst[e];
        float w = ew[e];
        unsigned wid = (unsigned)__ldg(&node_ids[s]);
        int p = atomicAdd(&g_count[d], 1);
        if (p < CAP) {
            uint2 pk;
            pk.x = (wid << 17) | (unsigned)s;
            pk.y = __float_as_uint(w);
            g_bedge[(size_t)d * CAP + p] = pk;
        }
    }
}

// ---------------- layer-1 aggregation + lrelu + dot-u (warp per node, fp8 rows) ----------
__global__ void k_agg1(const float* __restrict__ b1) {
    int warp = (blockIdx.x * blockDim.x + threadIdx.x) >> 5;
    int lane = threadIdx.x & 31;
    if (warp >= NT) return;
    int n = warp;
    int deg = min(g_count[n], CAP);
    const uint2* bucket = g_bedge + (size_t)n * CAP;

    float4 acc = make_float4(0.f, 0.f, 0.f, 0.f);
    float ews = 0.f;

    for (int base = 0; base < deg; base += 32) {
        int cnt = min(32, deg - base);
        uint2 e = make_uint2(0u, 0u);
        if (lane < cnt) e = __ldg(&bucket[base + lane]);
#pragma unroll 4
        for (int k = 0; k < cnt; ++k) {
            unsigned pk = __shfl_sync(0xffffffffu, e.x, k);
            float w = __uint_as_float(__shfl_sync(0xffffffffu, e.y, k));
            unsigned wid = pk >> 17;
            unsigned r = __ldg(reinterpret_cast<const unsigned*>(g_We1q + (size_t)wid * D) + lane);
            __half2_raw h0 = __nv_cvt_fp8x2_to_halfraw2((__nv_fp8x2_storage_t)(r & 0xFFFFu), __NV_E4M3);
            __half2_raw h1r = __nv_cvt_fp8x2_to_halfraw2((__nv_fp8x2_storage_t)(r >> 16), __NV_E4M3);
            float2 fa = __half22float2(*reinterpret_cast<__half2*>(&h0));
            float2 fb = __half22float2(*reinterpret_cast<__half2*>(&h1r));
            acc.x += w * fa.x; acc.y += w * fa.y;
            acc.z += w * fb.x; acc.w += w * fb.y;
            ews += w;
        }
    }

    float4 h1 = make_float4(0.f, 0.f, 0.f, 0.f);
    if (deg > 0) {
        float inv = 1.0f / (float)deg;
        float4 b4 = *reinterpret_cast<const float4*>(b1 + 4 * lane);
        h1.x = (acc.x + b4.x * ews) * inv;
        h1.y = (acc.y + b4.y * ews) * inv;
        h1.z = (acc.z + b4.z * ews) * inv;
        h1.w = (acc.w + b4.w * ews) * inv;
    }
    h1.x = h1.x > 0.f ? h1.x : 0.01f * h1.x;
    h1.y = h1.y > 0.f ? h1.y : 0.01f * h1.y;
    h1.z = h1.z > 0.f ? h1.z : 0.01f * h1.z;
    h1.w = h1.w > 0.f ? h1.w : 0.01f * h1.w;
    float4 u4 = *reinterpret_cast<const float4*>(g_u + 4 * lane);
    float zp = h1.x * u4.x + h1.y * u4.y + h1.z * u4.z + h1.w * u4.w;
#pragma unroll
    for (int o = 16; o > 0; o >>= 1) zp += __shfl_xor_sync(0xffffffffu, zp, o);
    if (lane == 0) g_z[n] = zp;
}

// ---------------- layer-2 scalar aggregation (warp per node) + pooled atomics ----------
__global__ void k_agg2pool() {
    int warp = (blockIdx.x * blockDim.x + threadIdx.x) >> 5;
    int lane = threadIdx.x & 31;
    if (warp >= NT) return;
    int n = warp;
    int deg = min(g_count[n], CAP);
    const uint2* bucket = g_bedge + (size_t)n * CAP;

    float t = 0.f, ews = 0.f;
    for (int base = 0; base < deg; base += 32) {
        int idx = base + lane;
        if (idx < deg) {
            uint2 e = __ldg(&bucket[idx]);
            float w = __uint_as_float(e.y);
            int s = (int)(e.x & 0x1FFFFu);
            t += w * __ldg(&g_z[s]);
            ews += w;
        }
    }
#pragma unroll
    for (int o = 16; o > 0; o >>= 1) {
        t   += __shfl_xor_sync(0xffffffffu, t, o);
        ews += __shfl_xor_sync(0xffffffffu, ews, o);
    }
    if (lane == 0) {
        float v = (deg > 0) ? (t + g_cscal * ews) / (float)deg : 0.f;
        atomicAdd(&g_gsum[n / NPG], v);
    }
}

// ---------------- loss + sigmoid ----------------
__global__ void k_final(const float* __restrict__ y, const float* __restrict__ b_out,
                        float* __restrict__ out) {
    __shared__ float sh[64];
    int t = threadIdx.x;
    float term = 0.f;
    if (t < NB) {
        float l = g_gsum[t] * (1.0f / (float)NPG) + b_out[0];
        term = fmaxf(l, 0.f) - l * y[t] + log1pf(expf(-fabsf(l)));
        out[1 + t] = 1.0f / (1.0f + expf(-l));
    }
    sh[t] = term;
    __syncthreads();
    for (int o = 32; o > 0; o >>= 1) {
        if (t < o) sh[t] += sh[t + o];
        __syncthreads();
    }
    if (t == 0) out[0] = sh[0] / (float)NB;
}

// ---------------- launch ----------------
extern "C" void kernel_launch(void* const* d_in, const int* in_sizes, int n_in,
                              void* d_out, int out_size) {
    const int*   node_ids = (const int*)  d_in[0];
    const int*   src      = (const int*)  d_in[1];
    const int*   dst      = (const int*)  d_in[2];
    const float* ew       = (const float*)d_in[3];
    const float* y_data   = (const float*)d_in[4];
    const float* embeds   = (const float*)d_in[5];
    const float* W1       = (const float*)d_in[6];
    const float* b1       = (const float*)d_in[7];
    const float* W2       = (const float*)d_in[8];
    const float* b2       = (const float*)d_in[9];
    const float* W_out    = (const float*)d_in[10];
    const float* b_out    = (const float*)d_in[11];
    float* out = (float*)d_out;

    (void)in_sizes; (void)n_in; (void)out_size;

    // fused: zero cursors/gsum | We1 GEMM (fp8) | u,c
    k_pre<<<PRE_GRID, 256>>>(embeds, W1, W2, W_out, b2);

    // single-pass bucket scatter (no count/scan kernels)
    k_scatter<<<2048, 256>>>(src, dst, ew, node_ids);

    // layer 1 fused: aggregate (fp8 rows) + bias + mean + lrelu + dot(u)
    k_agg1<<<NT / 8, 256>>>(b1);

    // layer 2 scalar aggregation + per-graph pool
    k_agg2pool<<<NT / 8, 256>>>();

    // loss + sigmoid
    k_final<<<1, 64>>>(y_data, b_out, out);
}

// round 17
// speedup vs baseline: 1.8454x; 1.8454x over previous
#include <cuda_runtime.h>
#include <cuda_fp16.h>
#include <cuda_fp8.h>
#include <math.h>

#define NT 100000
#define NB 50
#define NE 1600000
#define NV 15000
#define D  128
#define NPG (NT / NB)          // 2000 nodes per graph
#define CAP 64                 // bucket capacity per node (P[deg>64] ~ 1e-13)

#define ZBLK ((NT + 255) / 256)   // 391 zero blocks
#define GBLK 256                  // gemm blocks
#define PRE_GRID (ZBLK + GBLK + 1)

// ---------------- static device scratch (no allocations allowed) ----------------
__device__ __align__(16) unsigned char g_We1q[(size_t)NV * D]; // fp8 e4m3 word_embeds@W1 (1.9MB)
__device__ int   g_count[NT];                                  // write cursor -> deg
__device__ __align__(16) uint2 g_bedge[(size_t)NT * CAP];      // bucketed edges, 51.2MB
                                                               // .x = (wid<<17)|src, .y = f32 bits(w)
__device__ float g_z[NT];                                      // z[n] = lrelu(h1[n]) . u
__device__ __align__(16) float g_u[D];                         // u = W2 @ W_out
__device__ float g_cscal;                                      // c = b2 . W_out
__device__ __align__(16) float g_gsum[NB * 32];                // padded per-graph sums (stride 128B)

// ---------------- fused: zero counters | We1 GEMM (fp8 out) | u,c precompute ----------------
__global__ void k_pre(const float* __restrict__ emb, const float* __restrict__ W1,
                      const float* __restrict__ W2, const float* __restrict__ Wout,
                      const float* __restrict__ b2) {
    int bx = blockIdx.x;
    int tid = threadIdx.x;

    if (bx < ZBLK) {
        // ---- zero cursors + padded graph sums (block-strided: covers all NB*32) ----
        int i = bx * 256 + tid;
        if (i < NT) g_count[i] = 0;
        if (i < NB * 32) g_gsum[i] = 0.f;      // FIX: was `bx==0 && tid<NB*32` (only 256 zeroed)
        return;
    }
    if (bx < ZBLK + GBLK) {
        // ---- We1 = emb @ W1, fp8 e4m3 output, 4-row register blocking ----
        int lane = tid & 31;
        int warp = (bx - ZBLK) * 8 + (tid >> 5);   // 2048 warps
        const int nw = GBLK * 8;
        for (int rb = warp * 4; rb < NV; rb += nw * 4) {
            float4 h[4], acc[4];
#pragma unroll
            for (int r = 0; r < 4; ++r) {
                h[r] = *reinterpret_cast<const float4*>(emb + (size_t)(rb + r) * D + 4 * lane);
                acc[r] = make_float4(0.f, 0.f, 0.f, 0.f);
            }
#pragma unroll 2
            for (int q = 0; q < 32; ++q) {
                float4 w0 = __ldg(reinterpret_cast<const float4*>(W1 + (4 * q + 0) * D + 4 * lane));
                float4 w1 = __ldg(reinterpret_cast<const float4*>(W1 + (4 * q + 1) * D + 4 * lane));
                float4 w2 = __ldg(reinterpret_cast<const float4*>(W1 + (4 * q + 2) * D + 4 * lane));
                float4 w3 = __ldg(reinterpret_cast<const float4*>(W1 + (4 * q + 3) * D + 4 * lane));
#pragma unroll
                for (int r = 0; r < 4; ++r) {
                    float hx = __shfl_sync(0xffffffffu, h[r].x, q);
                    float hy = __shfl_sync(0xffffffffu, h[r].y, q);
                    float hz = __shfl_sync(0xffffffffu, h[r].z, q);
                    float hw = __shfl_sync(0xffffffffu, h[r].w, q);
                    acc[r].x += hx * w0.x + hy * w1.x + hz * w2.x + hw * w3.x;
                    acc[r].y += hx * w0.y + hy * w1.y + hz * w2.y + hw * w3.y;
                    acc[r].z += hx * w0.z + hy * w1.z + hz * w2.z + hw * w3.z;
                    acc[r].w += hx * w0.w + hy * w1.w + hz * w2.w + hw * w3.w;
                }
            }
#pragma unroll
            for (int r = 0; r < 4; ++r) {
                unsigned b0 = __nv_cvt_float_to_fp8(acc[r].x, __NV_SATFINITE, __NV_E4M3);
                unsigned b1 = __nv_cvt_float_to_fp8(acc[r].y, __NV_SATFINITE, __NV_E4M3);
                unsigned b2q = __nv_cvt_float_to_fp8(acc[r].z, __NV_SATFINITE, __NV_E4M3);
                unsigned b3 = __nv_cvt_float_to_fp8(acc[r].w, __NV_SATFINITE, __NV_E4M3);
                unsigned pk = b0 | (b1 << 8) | (b2q << 16) | (b3 << 24);
                reinterpret_cast<unsigned*>(g_We1q + (size_t)(rb + r) * D)[lane] = pk;
            }
        }
        return;
    }
    // ---- last block: u = W2 @ W_out, c = b2 . W_out ----
    if (tid < D) {
        float s = 0.f;
        for (int j = 0; j < D; ++j) s += W2[tid * D + j] * Wout[j];
        g_u[tid] = s;
    }
    if (tid == 0) {
        float c = 0.f;
        for (int j = 0; j < D; ++j) c += b2[j] * Wout[j];
        g_cscal = c;
    }
}

// ---------------- bucket scatter (single pass; cursor atomics double as deg) ----------------
__global__ void k_scatter(const int* __restrict__ src, const int* __restrict__ dst,
                          const float* __restrict__ ew,
                          const int* __restrict__ node_ids) {
    int stride = gridDim.x * blockDim.x;
    for (int e = blockIdx.x * blockDim.x + threadIdx.x; e < NE; e += stride) {
        int s = src[e];
        int d = dst[e];
        float w = ew[e];
        unsigned wid = (unsigned)__ldg(&node_ids[s]);
        int p = atomicAdd(&g_count[d], 1);
        if (p < CAP) {
            uint2 pk;
            pk.x = (wid << 17) | (unsigned)s;
            pk.y = __float_as_uint(w);
            g_bedge[(size_t)d * CAP + p] = pk;
        }
    }
}

// ---------------- layer-1 aggregation + lrelu + dot-u (warp per node, fp8 rows) ----------
__global__ void k_agg1(const float* __restrict__ b1) {
    int warp = (blockIdx.x * blockDim.x + threadIdx.x) >> 5;
    int lane = threadIdx.x & 31;
    if (warp >= NT) return;
    int n = warp;
    int deg = min(g_count[n], CAP);
    const uint2* bucket = g_bedge + (size_t)n * CAP;

    float4 acc = make_float4(0.f, 0.f, 0.f, 0.f);
    float ews = 0.f;

    for (int base = 0; base < deg; base += 32) {
        int cnt = min(32, deg - base);
        uint2 e = make_uint2(0u, 0u);
        if (lane < cnt) e = __ldg(&bucket[base + lane]);
#pragma unroll 4
        for (int k = 0; k < cnt; ++k) {
            unsigned pk = __shfl_sync(0xffffffffu, e.x, k);
            float w = __uint_as_float(__shfl_sync(0xffffffffu, e.y, k));
            unsigned wid = pk >> 17;
            unsigned r = __ldg(reinterpret_cast<const unsigned*>(g_We1q + (size_t)wid * D) + lane);
            __half2_raw h0 = __nv_cvt_fp8x2_to_halfraw2((__nv_fp8x2_storage_t)(r & 0xFFFFu), __NV_E4M3);
            __half2_raw h1r = __nv_cvt_fp8x2_to_halfraw2((__nv_fp8x2_storage_t)(r >> 16), __NV_E4M3);
            float2 fa = __half22float2(*reinterpret_cast<__half2*>(&h0));
            float2 fb = __half22float2(*reinterpret_cast<__half2*>(&h1r));
            acc.x += w * fa.x; acc.y += w * fa.y;
            acc.z += w * fb.x; acc.w += w * fb.y;
            ews += w;
        }
    }

    float4 h1 = make_float4(0.f, 0.f, 0.f, 0.f);
    if (deg > 0) {
        float inv = 1.0f / (float)deg;
        float4 b4 = *reinterpret_cast<const float4*>(b1 + 4 * lane);
        h1.x = (acc.x + b4.x * ews) * inv;
        h1.y = (acc.y + b4.y * ews) * inv;
        h1.z = (acc.z + b4.z * ews) * inv;
        h1.w = (acc.w + b4.w * ews) * inv;
    }
    h1.x = h1.x > 0.f ? h1.x : 0.01f * h1.x;
    h1.y = h1.y > 0.f ? h1.y : 0.01f * h1.y;
    h1.z = h1.z > 0.f ? h1.z : 0.01f * h1.z;
    h1.w = h1.w > 0.f ? h1.w : 0.01f * h1.w;
    float4 u4 = *reinterpret_cast<const float4*>(g_u + 4 * lane);
    float zp = h1.x * u4.x + h1.y * u4.y + h1.z * u4.z + h1.w * u4.w;
#pragma unroll
    for (int o = 16; o > 0; o >>= 1) zp += __shfl_xor_sync(0xffffffffu, zp, o);
    if (lane == 0) g_z[n] = zp;
}

// ---------------- layer-2 aggregation (warp per node) + block-pooled atomics ----------
// Block = 8 warps = 8 consecutive nodes. NPG (2000) % 8 == 0, so a block never
// straddles a graph boundary: ONE atomicAdd per block into padded g_gsum.
__global__ void k_agg2pool() {
    __shared__ float sh[8];
    int wid_b = threadIdx.x >> 5;
    int lane = threadIdx.x & 31;
    int n = blockIdx.x * 8 + wid_b;
    if (n >= NT) return;
    int deg = min(g_count[n], CAP);
    const uint2* bucket = g_bedge + (size_t)n * CAP;

    float t = 0.f, ews = 0.f;
    for (int base = 0; base < deg; base += 32) {
        int idx = base + lane;
        if (idx < deg) {
            uint2 e = __ldg(&bucket[idx]);
            float w = __uint_as_float(e.y);
            int s = (int)(e.x & 0x1FFFFu);
            t += w * __ldg(&g_z[s]);
            ews += w;
        }
    }
#pragma unroll
    for (int o = 16; o > 0; o >>= 1) {
        t   += __shfl_xor_sync(0xffffffffu, t, o);
        ews += __shfl_xor_sync(0xffffffffu, ews, o);
    }
    if (lane == 0)
        sh[wid_b] = (deg > 0) ? (t + g_cscal * ews) / (float)deg : 0.f;
    __syncthreads();
    if (threadIdx.x == 0) {
        float s = sh[0] + sh[1] + sh[2] + sh[3] + sh[4] + sh[5] + sh[6] + sh[7];
        int g = (blockIdx.x * 8) / NPG;        // constant over the block
        atomicAdd(&g_gsum[g * 32], s);
    }
}

// ---------------- loss + sigmoid ----------------
__global__ void k_final(const float* __restrict__ y, const float* __restrict__ b_out,
                        float* __restrict__ out) {
    __shared__ float sh[64];
    int t = threadIdx.x;
    float term = 0.f;
    if (t < NB) {
        float l = g_gsum[t * 32] * (1.0f / (float)NPG) + b_out[0];
        term = fmaxf(l, 0.f) - l * y[t] + log1pf(expf(-fabsf(l)));
        out[1 + t] = 1.0f / (1.0f + expf(-l));
    }
    sh[t] = term;
    __syncthreads();
    for (int o = 32; o > 0; o >>= 1) {
        if (t < o) sh[t] += sh[t + o];
        __syncthreads();
    }
    if (t == 0) out[0] = sh[0] / (float)NB;
}

// ---------------- launch ----------------
extern "C" void kernel_launch(void* const* d_in, const int* in_sizes, int n_in,
                              void* d_out, int out_size) {
    const int*   node_ids = (const int*)  d_in[0];
    const int*   src      = (const int*)  d_in[1];
    const int*   dst      = (const int*)  d_in[2];
    const float* ew       = (const float*)d_in[3];
    const float* y_data   = (const float*)d_in[4];
    const float* embeds   = (const float*)d_in[5];
    const float* W1       = (const float*)d_in[6];
    const float* b1       = (const float*)d_in[7];
    const float* W2       = (const float*)d_in[8];
    const float* b2       = (const float*)d_in[9];
    const float* W_out    = (const float*)d_in[10];
    const float* b_out    = (const float*)d_in[11];
    float* out = (float*)d_out;

    (void)in_sizes; (void)n_in; (void)out_size;

    // fused: zero cursors/gsum | We1 GEMM (fp8) | u,c
    k_pre<<<PRE_GRID, 256>>>(embeds, W1, W2, W_out, b2);

    // single-pass bucket scatter (no count/scan kernels)
    k_scatter<<<2048, 256>>>(src, dst, ew, node_ids);

    // layer 1 fused: aggregate (fp8 rows) + bias + mean + lrelu + dot(u)
    k_agg1<<<NT / 8, 256>>>(b1);

    // layer 2 aggregation + per-graph pool (1 atomic per block, padded bins)
    k_agg2pool<<<NT / 8, 256>>>();

    // loss + sigmoid
    k_final<<<1, 64>>>(y_data, b_out, out);
}